// round 17
// baseline (speedup 1.0000x reference)
#include <cuda_runtime.h>
#include <cuda_fp16.h>
#include <math.h>
#include <stdint.h>

// Problem constants
#define NUM_B 2
#define NUM_C 256
#define IMG_H 96
#define IMG_W 320
#define NLAYER 5
#define NQ (128 * 128)           // 16384
#define NM (NUM_B * NQ)          // 32768
#define NK (NUM_C * NLAYER)      // 1280
#define HW (IMG_H * IMG_W)       // 30720
#define NROWS (NUM_B * NUM_C * IMG_H)     // 49152
#define NBOX (NUM_B * NLAYER * NQ)        // 163840
#define NWP (NUM_C * NK)                  // 327680
#define NMT (NM / 64)                     // 512 M-tiles

// Scratch (device globals: allocation-free per harness rules)
__device__ float  g_rowcum[NUM_B * NUM_C * IMG_H * IMG_W];     // 63MB
__device__ float  g_itrans[NUM_B * IMG_H * IMG_W * NUM_C];     // 63MB, [b][y][x][c]
__device__ __align__(256) __half g_vox[NM * NK];               // 84MB, [m][k] fp16
__device__ __align__(256) __half g_wperm[NUM_C * NK];          // 0.65MB, [co][k] fp16
__device__ float  g_bpa[NBOX];                                 // visible ? 1/area : 0
__device__ int2   g_tap[NBOX * 16];                            // {pixel idx, weight bits}
__device__ unsigned g_vis[NMT];                                // per-Mtile layer visibility bits

__device__ __forceinline__ uint32_t smem_u32(const void* p) {
    uint32_t a;
    asm("{ .reg .u64 t; cvta.to.shared.u64 t, %1; cvt.u32.u64 %0, t; }" : "=r"(a) : "l"(p));
    return a;
}
__device__ __forceinline__ void cp16(uint32_t saddr, const void* gptr) {
    asm volatile("cp.async.cg.shared.global [%0], [%1], 16;" :: "r"(saddr), "l"(gptr) : "memory");
}
#define LDSM4(r, a) \
    asm volatile("ldmatrix.sync.aligned.m8n8.x4.shared.b16 {%0,%1,%2,%3}, [%4];" \
                 : "=r"((r)[0]), "=r"((r)[1]), "=r"((r)[2]), "=r"((r)[3]) : "r"(a))
__device__ __forceinline__ void mma_f16(float c[4], const uint32_t a[4], uint32_t b0, uint32_t b1) {
    asm volatile(
        "mma.sync.aligned.m16n8k16.row.col.f32.f16.f16.f32 "
        "{%0,%1,%2,%3}, {%4,%5,%6,%7}, {%8,%9}, {%0,%1,%2,%3};"
        : "+f"(c[0]), "+f"(c[1]), "+f"(c[2]), "+f"(c[3])
        : "r"(a[0]), "r"(a[1]), "r"(a[2]), "r"(a[3]), "r"(b0), "r"(b1));
}

// ---------------- K1a: row cumsum, warp-per-row, 2 elems/lane, batch-offset ----------------
__global__ __launch_bounds__(512) void k_rowcum(const float* __restrict__ feat, int w_off) {
    int w = w_off + blockIdx.x * 16 + (threadIdx.x >> 5);
    int lane = threadIdx.x & 31;
    const float2* src = (const float2*)(feat + (size_t)w * IMG_W);
    float2* dst = (float2*)(g_rowcum + (size_t)w * IMG_W);
    float carry = 0.0f;
    #pragma unroll
    for (int c = 0; c < 5; ++c) {
        float2 v = src[c * 32 + lane];
        float s = v.x + v.y;
        float incl = s;
        #pragma unroll
        for (int d = 1; d < 32; d <<= 1) {
            float n = __shfl_up_sync(0xFFFFFFFFu, incl, d);
            if (lane >= d) incl += n;
        }
        float excl = incl - s;
        float lo = carry + excl + v.x;
        float hi = lo + v.y;
        dst[c * 32 + lane] = make_float2(lo, hi);
        carry += __shfl_sync(0xFFFFFFFFu, incl, 31);
    }
}

// ---------------- K1b: prep (boxes tap table + vis bits + Wc permute) ----------------
#define PREP_BLOCKS ((NBOX + NWP + 255) / 256)

__global__ __launch_bounds__(256) void k_prep(const float* __restrict__ calib,
                                              const float* __restrict__ grid,
                                              const float* __restrict__ Wc) {
    int gi = blockIdx.x * blockDim.x + threadIdx.x;
    if (gi >= NBOX) {
        int idx = gi - NBOX;
        if (idx < NWP) {
            int co = idx / NK;
            int kd = idx % NK;
            int layer = kd / NUM_C;
            int c = kd % NUM_C;
            g_wperm[(size_t)co * NK + layer * NUM_C + c] = __float2half(Wc[co * NK + c * NLAYER + layer]);
        }
        return;
    }
    int i = gi;
    int q = i % NQ;
    int layer = (i / NQ) % NLAYER;
    int b = i / (NQ * NLAYER);

    float gx = grid[q * 3 + 0];
    float gy = grid[q * 3 + 1];
    float gz = grid[q * 3 + 2] + 32.0f * (float)layer;

    const float* M = calib + b * 12;
    float m00 = M[0], m01 = M[1], m02 = M[2],  m03 = M[3];
    float m10 = M[4], m11 = M[5], m12 = M[6],  m13 = M[7];
    float m20 = M[8], m21 = M[9], m22 = M[10], m23 = M[11];

    const float ox[8] = {-12.5f, 12.5f, 12.5f, -12.5f, -12.5f, 12.5f, 12.5f, -12.5f};
    const float oy[8] = {-12.5f, -12.5f, 12.5f, 12.5f, -12.5f, -12.5f, 12.5f, 12.5f};
    const float oz[8] = {0.0f, 0.0f, 0.0f, 0.0f, 32.0f, 32.0f, 32.0f, 32.0f};

    float mnx = 1e30f, mny = 1e30f, mxx = -1e30f, mxy = -1e30f;
    #pragma unroll
    for (int k = 0; k < 8; ++k) {
        float X = gx + ox[k];
        float Y = gy + oy[k];
        float Z = gz + oz[k];
        float px = m00 * X + m01 * Y + m02 * Z + m03;
        float py = m10 * X + m11 * Y + m12 * Z + m13;
        float pz = m20 * X + m21 * Y + m22 * Z + m23;
        float zc = fmaxf(pz, 1e-6f);
        float ix = px / zc;
        float iy = py / zc;
        float nx = fminf(fmaxf(2.0f * ix / 320.0f - 1.0f, -1.0f), 0.95f);
        float ny = fminf(fmaxf(2.0f * iy / 96.0f - 1.0f, -1.0f), 0.95f);
        mnx = fminf(mnx, nx);
        mny = fminf(mny, ny);
        mxx = fmaxf(mxx, nx);
        mxy = fmaxf(mxy, ny);
    }

    float area = ((mxx - mnx) * (mxy - mny)) * (float)HW + 1e-6f;
    bool visible = (area > 1e-6f) && (area < (float)HW * 0.3f);
    float inv = visible ? (1.0f / area) : 0.0f;
    g_bpa[i] = inv;
    if (visible)
        atomicOr(&g_vis[(b * NQ + q) >> 6], 1u << layer);

    float xs[2], ys[2];
    xs[0] = ((mnx + 1.0f) * 320.0f - 1.0f) * 0.5f;
    xs[1] = ((mxx + 1.0f) * 320.0f - 1.0f) * 0.5f;
    ys[0] = ((mny + 1.0f) * 96.0f - 1.0f) * 0.5f;
    ys[1] = ((mxy + 1.0f) * 96.0f - 1.0f) * 0.5f;

    // corners: lt(min,min,+), rb(max,max,+), rt(max,min,-), lb(min,max,-)
    const int cxi[4] = {0, 1, 1, 0};
    const int cyi[4] = {0, 1, 0, 1};
    const float csg[4] = {1.0f, 1.0f, -1.0f, -1.0f};
    int2* tp = g_tap + (size_t)i * 16;
    #pragma unroll
    for (int cc = 0; cc < 4; ++cc) {
        float sx = xs[cxi[cc]], sy = ys[cyi[cc]];
        float fx = floorf(sx), fy = floorf(sy);
        int x0 = (int)fx, y0 = (int)fy;
        float wx1 = sx - fx, wy1 = sy - fy;
        float wx0 = 1.0f - wx1, wy0 = 1.0f - wy1;
        float s = csg[cc] * inv;
        #pragma unroll
        for (int tt = 0; tt < 4; ++tt) {
            int xi = x0 + (tt & 1);
            int yi = y0 + (tt >> 1);
            float w = ((tt & 1) ? wx1 : wx0) * ((tt >> 1) ? wy1 : wy0) * s;
            bool valid = visible && ((unsigned)xi < (unsigned)IMG_W) && ((unsigned)yi < (unsigned)IMG_H);
            int idx = valid ? (yi * IMG_W + xi) : 0;
            if (!valid) w = 0.0f;
            tp[cc * 4 + tt] = make_int2(idx, __float_as_int(w));
        }
    }
}

// ---------------- K2: column cumsum + transpose, (16x,16c) tiles, per-batch ----------------
__global__ __launch_bounds__(256) void k_colcum_t(int b) {
    __shared__ float tile[8][16][17];
    int x0 = blockIdx.x * 16;
    int c0 = blockIdx.y * 16;
    int tx = threadIdx.x, ty = threadIdx.y;   // read: x = x0+tx, c = c0+ty
    const float* src = g_rowcum + ((size_t)(b * NUM_C + c0 + ty) * IMG_H) * IMG_W + x0 + tx;
    float* dstbase = g_itrans + (size_t)b * HW * NUM_C;
    float acc = 0.0f;
    for (int y0 = 0; y0 < IMG_H; y0 += 8) {
        float v[8];
        #pragma unroll
        for (int j = 0; j < 8; ++j) v[j] = src[(size_t)(y0 + j) * IMG_W];
        #pragma unroll
        for (int j = 0; j < 8; ++j) { acc += v[j]; tile[j][ty][tx] = acc; }
        __syncthreads();
        // write: x = x0+ty, c = c0+tx
        #pragma unroll
        for (int j = 0; j < 8; ++j)
            dstbase[((size_t)(y0 + j) * IMG_W + x0 + ty) * NUM_C + c0 + tx] = tile[j][tx][ty];
        __syncthreads();
    }
}

// ---------------- K4: sampling -> vox (fp16), vis-gated, m-offset ----------
__global__ __launch_bounds__(256) void k_sample(int m_off) {
    __shared__ int2 st[2][NLAYER][16];
    __shared__ float sinv[2][NLAYER];
    int m0 = m_off + blockIdx.x * 2;
    int b = m0 >> 14;
    int q0 = m0 & (NQ - 1);
    int tid = threadIdx.x;

    unsigned visw = g_vis[m0 >> 6];
    if (visw == 0) return;          // GEMM never reads any layer of this tile

    if (tid < 2 * NLAYER * 16) {
        int pair = tid / 80;
        int rem = tid % 80;
        int layer = rem >> 4, t = rem & 15;
        if ((visw >> layer) & 1u)
            st[pair][layer][t] = g_tap[((size_t)((b * NLAYER + layer) * NQ + q0 + pair)) * 16 + t];
    } else if (tid >= 192 && tid < 192 + 2 * NLAYER) {
        int e = tid - 192;
        int pair = e / NLAYER, layer = e % NLAYER;
        sinv[pair][layer] = g_bpa[(size_t)(b * NLAYER + layer) * NQ + q0 + pair];
    }
    __syncthreads();

    int pair = tid >> 7;
    int ch = tid & 127;
    int m = m0 + pair;
    const float2* I2 = (const float2*)(g_itrans + (size_t)b * HW * NUM_C) + ch;
    __half2* vdst = (__half2*)(g_vox + (size_t)m * NK) + ch;

    #pragma unroll
    for (int layer = 0; layer < NLAYER; ++layer) {
        if (!((visw >> layer) & 1u)) continue;   // chunk never read by GEMM
        float vx = 0.0f, vy = 0.0f;
        if (sinv[pair][layer] != 0.0f) {
            float2 d[16];
            #pragma unroll
            for (int t = 0; t < 16; ++t)
                d[t] = I2[(size_t)st[pair][layer][t].x * 128];
            float ax0 = 0.0f, ax1 = 0.0f, ax2 = 0.0f, ax3 = 0.0f;
            float ay0 = 0.0f, ay1 = 0.0f, ay2 = 0.0f, ay3 = 0.0f;
            #pragma unroll
            for (int t = 0; t < 4; ++t) {
                float f0 = __int_as_float(st[pair][layer][t].y);
                float f1 = __int_as_float(st[pair][layer][4 + t].y);
                float f2 = __int_as_float(st[pair][layer][8 + t].y);
                float f3 = __int_as_float(st[pair][layer][12 + t].y);
                ax0 = fmaf(d[t].x, f0, ax0);      ay0 = fmaf(d[t].y, f0, ay0);
                ax1 = fmaf(d[4 + t].x, f1, ax1);  ay1 = fmaf(d[4 + t].y, f1, ay1);
                ax2 = fmaf(d[8 + t].x, f2, ax2);  ay2 = fmaf(d[8 + t].y, f2, ay2);
                ax3 = fmaf(d[12 + t].x, f3, ax3); ay3 = fmaf(d[12 + t].y, f3, ay3);
            }
            vx = (ax0 + ax1) + (ax2 + ax3);
            vy = (ay0 + ay1) + (ay2 + ay3);
        }
        vdst[layer * 128] = __floats2half2_rn(vx, vy);
    }
}

// ---------------- K6: fp16 mma GEMM (CTA 64Mx128N), vis-compacted K, Mtile offset ----------
#define STAGE_BYTES 24576
#define A_BYTES 8192
#define GSM_BYTES (3 * STAGE_BYTES)
#define NKT (NK / 64)   // 20

__global__ __launch_bounds__(256, 3) void k_gemm(const float* __restrict__ bc,
                                                 float* __restrict__ out, int mt_off) {
    extern __shared__ char smc[];
    __shared__ int s_list[NKT];
    __shared__ int s_n;
    uint32_t smb = smem_u32(smc);
    int tid = threadIdx.x;
    int wid = tid >> 5;
    int lane = tid & 31;
    int g = lane >> 2;
    int tg = lane & 3;
    int wm = wid & 1;          // 2 M halves (32 rows each)
    int wn = wid >> 1;         // 4 N quarters (32 cols each)
    int mt = mt_off + blockIdx.y;
    int n0 = blockIdx.x * 128;
    int m0 = mt * 64;

    if (tid == 0) {
        unsigned vis = g_vis[mt];
        int n = 0;
        #pragma unroll
        for (int kt = 0; kt < NKT; ++kt)
            if ((vis >> (kt >> 2)) & 1u) s_list[n++] = kt;
        s_n = n;
    }
    __syncthreads();
    int nact = s_n;

    float acc[2][4][4];
    #pragma unroll
    for (int ms = 0; ms < 2; ++ms)
        #pragma unroll
        for (int ns = 0; ns < 4; ++ns)
            #pragma unroll
            for (int cc = 0; cc < 4; ++cc) acc[ms][ns][cc] = 0.0f;

    int a_row_l = wm * 32 + (lane & 7) + (((lane >> 3) & 1) << 3);
    int a_cadd  = lane >> 4;
    int b_row_l = wn * 32 + (lane & 7) + ((lane >> 4) << 3);
    int b_cadd  = (lane >> 3) & 1;

    #define FILL(slot, ktv) do { \
        int _kt = (ktv); \
        uint32_t _sb = smb + (uint32_t)((slot) * STAGE_BYTES); \
        int _ko = _kt * 64; \
        _Pragma("unroll") \
        for (int _i = 0; _i < 2; ++_i) { \
            int _idx = tid + _i * 256; \
            int _row = _idx >> 3, _c16 = _idx & 7; \
            cp16(_sb + (uint32_t)(_row * 128 + ((_c16 ^ (_row & 7)) << 4)), \
                 (const char*)g_vox + ((size_t)(m0 + _row) * NK + _ko) * 2 + _c16 * 16); \
        } \
        _Pragma("unroll") \
        for (int _i = 0; _i < 4; ++_i) { \
            int _idx = tid + _i * 256; \
            int _row = _idx >> 3, _c16 = _idx & 7; \
            cp16(_sb + (uint32_t)A_BYTES + (uint32_t)(_row * 128 + ((_c16 ^ (_row & 7)) << 4)), \
                 (const char*)g_wperm + ((size_t)(n0 + _row) * NK + _ko) * 2 + _c16 * 16); \
        } \
        asm volatile("cp.async.commit_group;" ::: "memory"); \
    } while (0)

    if (nact > 0) FILL(0, s_list[0]);
    if (nact > 1) FILL(1, s_list[1]);

    for (int it = 0; it < nact; ++it) {
        if (it + 2 < nact) {
            FILL((it + 2) % 3, s_list[it + 2]);
            asm volatile("cp.async.wait_group 2;" ::: "memory");
        } else if (it + 1 < nact) {
            asm volatile("cp.async.wait_group 1;" ::: "memory");
        } else {
            asm volatile("cp.async.wait_group 0;" ::: "memory");
        }
        __syncthreads();

        uint32_t sA = smb + (uint32_t)((it % 3) * STAGE_BYTES);
        uint32_t sB = sA + (uint32_t)A_BYTES;
        #pragma unroll
        for (int ks = 0; ks < 4; ++ks) {
            uint32_t a[2][4];
            #pragma unroll
            for (int ms = 0; ms < 2; ++ms) {
                int row = a_row_l + ms * 16;
                int c16 = 2 * ks + a_cadd;
                LDSM4(a[ms], sA + (uint32_t)(row * 128 + ((c16 ^ (row & 7)) << 4)));
            }
            uint32_t bf[2][4];
            #pragma unroll
            for (int np = 0; np < 2; ++np) {
                int row = b_row_l + np * 16;
                int c16 = 2 * ks + b_cadd;
                LDSM4(bf[np], sB + (uint32_t)(row * 128 + ((c16 ^ (row & 7)) << 4)));
            }
            #pragma unroll
            for (int ms = 0; ms < 2; ++ms)
                #pragma unroll
                for (int ns = 0; ns < 4; ++ns)
                    mma_f16(acc[ms][ns], a[ms], bf[ns >> 1][(ns & 1) * 2], bf[ns >> 1][(ns & 1) * 2 + 1]);
        }
        __syncthreads();
    }

    // Epilogue: out[b][n][q] = relu(acc + bc[n])
    int b = m0 >> 14;
    #pragma unroll
    for (int ms = 0; ms < 2; ++ms) {
        #pragma unroll
        for (int h = 0; h < 2; ++h) {
            int m = m0 + wm * 32 + ms * 16 + g + h * 8;
            int q = m & (NQ - 1);
            float* ob = out + (size_t)b * NUM_C * NQ + q;
            #pragma unroll
            for (int ns = 0; ns < 4; ++ns) {
                int n = n0 + wn * 32 + ns * 8 + tg * 2;
                float v0 = acc[ms][ns][h * 2 + 0] + __ldg(bc + n);
                float v1 = acc[ms][ns][h * 2 + 1] + __ldg(bc + n + 1);
                ob[(size_t)n * NQ] = fmaxf(v0, 0.0f);
                ob[(size_t)(n + 1) * NQ] = fmaxf(v1, 0.0f);
            }
        }
    }
}

extern "C" void kernel_launch(void* const* d_in, const int* in_sizes, int n_in,
                              void* d_out, int out_size) {
    const float* feature = (const float*)d_in[0];  // (2,256,96,320)
    const float* calib   = (const float*)d_in[1];  // (2,3,4)
    const float* grid    = (const float*)d_in[2];  // (128,128,3)
    const float* Wc      = (const float*)d_in[3];  // (256,1280)
    const float* bc      = (const float*)d_in[4];  // (256,)
    float* out = (float*)d_out;                    // (2,256,128,128)

    static cudaStream_t s2 = nullptr, s3 = nullptr, sp = nullptr;
    static cudaEvent_t ev_fork = nullptr, ev_prep = nullptr, ev_i0 = nullptr, ev_i1 = nullptr;
    static cudaEvent_t ev_d2 = nullptr, ev_d3 = nullptr, ev_dp = nullptr;
    if (s2 == nullptr) {
        cudaStreamCreateWithFlags(&s2, cudaStreamNonBlocking);
        cudaStreamCreateWithFlags(&s3, cudaStreamNonBlocking);
        cudaStreamCreateWithFlags(&sp, cudaStreamNonBlocking);
        cudaEventCreateWithFlags(&ev_fork, cudaEventDisableTiming);
        cudaEventCreateWithFlags(&ev_prep, cudaEventDisableTiming);
        cudaEventCreateWithFlags(&ev_i0, cudaEventDisableTiming);
        cudaEventCreateWithFlags(&ev_i1, cudaEventDisableTiming);
        cudaEventCreateWithFlags(&ev_d2, cudaEventDisableTiming);
        cudaEventCreateWithFlags(&ev_d3, cudaEventDisableTiming);
        cudaEventCreateWithFlags(&ev_dp, cudaEventDisableTiming);
        cudaFuncSetAttribute(k_gemm, cudaFuncAttributeMaxDynamicSharedMemorySize, GSM_BYTES);
    }

    void* visptr = nullptr;
    cudaGetSymbolAddress(&visptr, g_vis);

    // Fork branches off the capture stream.
    cudaEventRecord(ev_fork, 0);
    cudaStreamWaitEvent(s2, ev_fork, 0);
    cudaStreamWaitEvent(s3, ev_fork, 0);
    cudaStreamWaitEvent(sp, ev_fork, 0);

    // Branch sp: prep (vis memset + boxes/wperm)
    cudaMemsetAsync(visptr, 0, NMT * sizeof(unsigned), sp);
    k_prep<<<PREP_BLOCKS, 256, 0, sp>>>(calib, grid, Wc);
    cudaEventRecord(ev_prep, sp);

    // Branch s0: integral batch 0
    k_rowcum<<<NROWS / 32, 512>>>(feature, 0);
    {
        dim3 g(IMG_W / 16, NUM_C / 16, 1);
        dim3 blk(16, 16);
        k_colcum_t<<<g, blk>>>(0);
    }
    cudaEventRecord(ev_i0, 0);

    // Branch s2: integral batch 1
    k_rowcum<<<NROWS / 32, 512, 0, s2>>>(feature, NROWS / 2);
    {
        dim3 g(IMG_W / 16, NUM_C / 16, 1);
        dim3 blk(16, 16);
        k_colcum_t<<<g, blk, 0, s2>>>(1);
    }
    cudaEventRecord(ev_i1, s2);

    // Chunk 0 (b0 lower) on stream 0
    cudaStreamWaitEvent(0, ev_prep, 0);
    k_sample<<<NM / 8, 256>>>(0);
    {
        dim3 gg(NUM_C / 128, NMT / 4);
        k_gemm<<<gg, 256, GSM_BYTES>>>(bc, out, 0);
    }

    // Chunk 1 (b0 upper) on s3
    cudaStreamWaitEvent(s3, ev_prep, 0);
    cudaStreamWaitEvent(s3, ev_i0, 0);
    k_sample<<<NM / 8, 256, 0, s3>>>(NM / 4);
    {
        dim3 gg(NUM_C / 128, NMT / 4);
        k_gemm<<<gg, 256, GSM_BYTES, s3>>>(bc, out, NMT / 4);
    }
    cudaEventRecord(ev_d3, s3);

    // Chunk 2 (b1 lower) on s2
    cudaStreamWaitEvent(s2, ev_prep, 0);
    k_sample<<<NM / 8, 256, 0, s2>>>(NM / 2);
    {
        dim3 gg(NUM_C / 128, NMT / 4);
        k_gemm<<<gg, 256, GSM_BYTES, s2>>>(bc, out, NMT / 2);
    }
    cudaEventRecord(ev_d2, s2);

    // Chunk 3 (b1 upper) on sp
    cudaStreamWaitEvent(sp, ev_i1, 0);
    k_sample<<<NM / 8, 256, 0, sp>>>(3 * NM / 4);
    {
        dim3 gg(NUM_C / 128, NMT / 4);
        k_gemm<<<gg, 256, GSM_BYTES, sp>>>(bc, out, 3 * NMT / 4);
    }
    cudaEventRecord(ev_dp, sp);

    // Join everything back to the capture stream.
    cudaStreamWaitEvent(0, ev_d3, 0);
    cudaStreamWaitEvent(0, ev_d2, 0);
    cudaStreamWaitEvent(0, ev_dp, 0);
}